// round 1
// baseline (speedup 1.0000x reference)
#include <cuda_runtime.h>
#include <math.h>

// ---------------------------------------------------------------------------
// Swin block: B=8, H=W=256, C=48, NH=3 (hd=16), WS=8 (N=64), SS=4, HID=192
// Kernel A: per-window fused  LN1 -> qkv -> windowed attention (+rpb +shift
//           mask) -> SE -> proj, scattered into scratch at original pixels.
// Kernel B: per-token residual + LN2 + MLP (fc1 -> exact GELU -> fc2) + res.
// ---------------------------------------------------------------------------

#define BB    8
#define HH    256
#define WWD   256
#define CC    48
#define NHEAD 3
#define HDIM  16
#define SSH   4
#define NTOK  64
#define NWH   32
#define NWIN  1024   // 32*32
#define BN    8192   // BB*NWIN
#define HIDDEN 192

// scratch for attention-branch output (written once per pixel, bijective map)
__device__ float g_attn[(size_t)BB * HH * WWD * CC];

// padded smem row strides (odd -> conflict-free per-lane rows)
#define SX  49
#define SQ  145
#define SSC 65

// dynamic smem float counts
#define A_SMEM_FLOATS (64*SX + 64*SQ + 64*SSC + 144*48 + 48*48 + 675 \
                       + 48 + 48 + 144 + 48 + 144 + 4 + 144 + 48 + 48 + 48 + 4)
#define B_SMEM_FLOATS (192*48 + 192*48 + 192 + 48 + 48 + 48)

__global__ void __launch_bounds__(64) attn_kernel(
    const float* __restrict__ x,
    const float* __restrict__ g1,   const float* __restrict__ b1,
    const float* __restrict__ qkvw, const float* __restrict__ qkvb,
    const float* __restrict__ rpbt, const float* __restrict__ wf,
    const float* __restrict__ sw1,  const float* __restrict__ sb1,
    const float* __restrict__ sw2,  const float* __restrict__ sb2,
    const float* __restrict__ pw,   const float* __restrict__ pb)
{
    extern __shared__ float sm[];
    float* s_x   = sm;                    // 64*SX   LN'd window tokens
    float* s_qkv = s_x   + 64*SX;         // 64*SQ   per-token qkv (144)
    float* s_sc  = s_qkv + 64*SQ;         // 64*SSC  per-row attn scores
    float* s_wq  = s_sc  + 64*SSC;        // 144*48  qkv weights
    float* s_pw  = s_wq  + 144*48;        // 48*48   proj weights
    float* s_rpb = s_pw  + 48*48;         // 675     rpb table (225 x 3)
    float* s_g1  = s_rpb + 675;           // 48
    float* s_b1  = s_g1  + 48;            // 48
    float* s_qb  = s_b1  + 48;            // 144
    float* s_pb  = s_qb  + 144;           // 48
    float* s_sw1 = s_pb  + 48;            // 144
    float* s_sb1 = s_sw1 + 144;           // 4
    float* s_sw2 = s_sb1 + 4;             // 144
    float* s_sb2 = s_sw2 + 144;           // 48
    float* s_mean= s_sb2 + 48;            // 48
    float* s_se  = s_mean+ 48;            // 48
    float* s_hh  = s_se  + 48;            // 4

    const int tid = threadIdx.x;

    // ---- stage constants into SMEM -------------------------------------
    for (int i = tid; i < 144*48; i += 64) s_wq[i] = qkvw[i];
    for (int i = tid; i < 48*48;  i += 64) s_pw[i] = pw[i];
    for (int i = tid; i < 675;    i += 64) s_rpb[i] = rpbt[i];
    if (tid < 48) {
        s_g1[tid] = g1[tid]; s_b1[tid] = b1[tid];
        s_pb[tid] = pb[tid]; s_sb2[tid] = sb2[tid];
    }
    for (int i = tid; i < 144; i += 64) {
        s_qb[i] = qkvb[i]; s_sw1[i] = sw1[i]; s_sw2[i] = sw2[i];
    }
    if (tid < 3) s_sb1[tid] = sb1[tid];

    // ---- window / pixel coordinates ------------------------------------
    const int blk = blockIdx.x;
    const int b  = blk / NWIN;
    const int w  = blk % NWIN;
    const int wy = w / NWH, wx = w % NWH;
    const int ti = tid >> 3, tj = tid & 7;
    const int gy = (wy*8 + ti + SSH) & 255;
    const int gx = (wx*8 + tj + SSH) & 255;
    const float* xrow = x + ((size_t)b*(HH*WWD) + gy*WWD + gx) * CC;

    // ---- load + LN1 ------------------------------------------------------
    float xr[48];
    float mu = 0.f, sq = 0.f;
    #pragma unroll
    for (int c = 0; c < 48; c += 4) {
        float4 v = *(const float4*)(xrow + c);
        xr[c]=v.x; xr[c+1]=v.y; xr[c+2]=v.z; xr[c+3]=v.w;
        mu += v.x + v.y + v.z + v.w;
        sq += v.x*v.x + v.y*v.y + v.z*v.z + v.w*v.w;
    }
    mu *= (1.f/48.f);
    float var = sq*(1.f/48.f) - mu*mu;
    float inv = rsqrtf(var + 1e-5f);

    __syncthreads();  // staging done

    #pragma unroll
    for (int c = 0; c < 48; c++) {
        xr[c] = (xr[c] - mu) * inv * s_g1[c] + s_b1[c];
        s_x[tid*SX + c] = xr[c];
    }
    __syncthreads();

    // ---- qkv = xw @ W^T + b  (per token, 144 outputs) -------------------
    for (int o = 0; o < 144; o++) {
        float acc = s_qb[o];
        const float* wr = s_wq + o*48;
        #pragma unroll
        for (int c = 0; c < 48; c++) acc += xr[c]*wr[c];
        s_qkv[tid*SQ + o] = acc;
    }
    __syncthreads();

    // ---- SE branch (mean over tokens of LN'd input) ----------------------
    if (tid < 48) {
        float s = 0.f;
        for (int t = 0; t < 64; t++) s += s_x[t*SX + tid];
        s_mean[tid] = s * (1.f/64.f);
    }
    __syncthreads();
    if (tid < 3) {
        float a = s_sb1[tid];
        #pragma unroll
        for (int c = 0; c < 48; c++) a += s_mean[c]*s_sw1[tid*48 + c];
        s_hh[tid] = fmaxf(a, 0.f);
    }
    __syncthreads();
    if (tid < 48) {
        float a = s_sb2[tid] + s_hh[0]*s_sw2[tid*3+0]
                             + s_hh[1]*s_sw2[tid*3+1]
                             + s_hh[2]*s_sw2[tid*3+2];
        s_se[tid] = 1.f/(1.f + expf(-a));
    }
    __syncthreads();

    // ---- attention: thread = query row ----------------------------------
    float out[48];
    #pragma unroll
    for (int c = 0; c < 48; c++) out[c] = 0.f;

    const int regy = (wy == 31) ? (ti >= 4 ? 2 : 1) : 0;
    const int regx = (wx == 31) ? (tj >= 4 ? 2 : 1) : 0;
    const float scale = 0.25f;  // hd^-0.5, hd=16
    float* myrow = s_sc + tid*SSC;

    for (int h = 0; h < 3; h++) {
        float qr[16];
        #pragma unroll
        for (int d = 0; d < 16; d++) qr[d] = s_qkv[tid*SQ + h*16 + d] * scale;

        float mx = -1e30f;
        for (int j = 0; j < 64; j++) {
            const float* kr = s_qkv + j*SQ + 48 + h*16;
            float s = 0.f;
            #pragma unroll
            for (int d = 0; d < 16; d++) s += qr[d]*kr[d];
            const int rj = j >> 3, cj = j & 7;
            s += s_rpb[((ti - rj + 7)*15 + (tj - cj + 7))*3 + h];
            const int ryj = (wy == 31) ? (rj >= 4 ? 2 : 1) : 0;
            const int rxj = (wx == 31) ? (cj >= 4 ? 2 : 1) : 0;
            if (ryj != regy || rxj != regx) s -= 100.f;
            myrow[j] = s;
            mx = fmaxf(mx, s);
        }
        float sum = 0.f;
        for (int j = 0; j < 64; j++) {
            float e = expf(myrow[j] - mx);
            myrow[j] = e;
            sum += e;
        }
        const float is = 1.f / sum;
        for (int j = 0; j < 64; j++) {
            const float wgt = myrow[j] * is;
            const float* vr = s_qkv + j*SQ + 96 + h*16;
            #pragma unroll
            for (int d = 0; d < 16; d++) out[h*16 + d] += wgt*vr[d];
        }
    }

    // ---- SE add ----------------------------------------------------------
    const float wfv = wf[0];
    #pragma unroll
    for (int c = 0; c < 48; c++) out[c] += wfv * xr[c] * s_se[c];

    // ---- proj + scatter to scratch at original pixel ---------------------
    float* orow = g_attn + ((size_t)b*(HH*WWD) + gy*WWD + gx) * CC;
    #pragma unroll
    for (int c4 = 0; c4 < 48; c4 += 4) {
        float4 r;
        #pragma unroll
        for (int k = 0; k < 4; k++) {
            const int cp = c4 + k;
            float a = s_pb[cp];
            const float* wr = s_pw + cp*48;
            #pragma unroll
            for (int c = 0; c < 48; c++) a += out[c]*wr[c];
            ((float*)&r)[k] = a;
        }
        *(float4*)(orow + c4) = r;
    }
}

__global__ void __launch_bounds__(256) mlp_kernel(
    const float* __restrict__ x,
    const float* __restrict__ g2,   const float* __restrict__ b2,
    const float* __restrict__ f1w,  const float* __restrict__ f1b,
    const float* __restrict__ f2w,  const float* __restrict__ f2b,
    float* __restrict__ out)
{
    extern __shared__ float sm[];
    float* s_f1 = sm;                 // 192*48
    float* s_f2 = s_f1 + 192*48;      // 192*48, transposed to [o][c]
    float* s_1b = s_f2 + 192*48;      // 192
    float* s_2b = s_1b + 192;         // 48
    float* s_g2 = s_2b + 48;          // 48
    float* s_b2 = s_g2 + 48;          // 48

    const int tid = threadIdx.x;
    for (int i = tid; i < 192*48; i += 256) s_f1[i] = f1w[i];
    for (int i = tid; i < 192*48; i += 256) {
        const int o = i / 48, c = i % 48;
        s_f2[i] = f2w[c*192 + o];
    }
    if (tid < 192) s_1b[tid] = f1b[tid];
    if (tid < 48) { s_2b[tid] = f2b[tid]; s_g2[tid] = g2[tid]; s_b2[tid] = b2[tid]; }
    __syncthreads();

    const size_t tok = (size_t)blockIdx.x*256 + tid;
    const float* xrow = x      + tok*48;
    const float* hrow = g_attn + tok*48;

    float xr[48], xln[48];
    float mu = 0.f, sq = 0.f;
    #pragma unroll
    for (int c = 0; c < 48; c += 4) {
        float4 a = *(const float4*)(xrow + c);
        float4 h = *(const float4*)(hrow + c);
        float v0 = a.x + h.x, v1 = a.y + h.y, v2 = a.z + h.z, v3 = a.w + h.w;
        xr[c]=v0; xr[c+1]=v1; xr[c+2]=v2; xr[c+3]=v3;
        mu += v0+v1+v2+v3;
        sq += v0*v0 + v1*v1 + v2*v2 + v3*v3;
    }
    mu *= (1.f/48.f);
    const float var = sq*(1.f/48.f) - mu*mu;
    const float inv = rsqrtf(var + 1e-5f);
    #pragma unroll
    for (int c = 0; c < 48; c++)
        xln[c] = (xr[c] - mu) * inv * s_g2[c] + s_b2[c];

    float acc[48];
    #pragma unroll
    for (int c = 0; c < 48; c++) acc[c] = 0.f;

    for (int o = 0; o < 192; o++) {
        float hsum = s_1b[o];
        const float* w1 = s_f1 + o*48;
        #pragma unroll
        for (int c = 0; c < 48; c++) hsum += xln[c]*w1[c];
        // exact GELU
        const float g = 0.5f * hsum * (1.f + erff(hsum * 0.70710678118654752f));
        const float* w2 = s_f2 + o*48;
        #pragma unroll
        for (int c = 0; c < 48; c++) acc[c] += g*w2[c];
    }

    float* orow = out + tok*48;
    #pragma unroll
    for (int c = 0; c < 48; c += 4) {
        float4 r;
        r.x = xr[c]   + acc[c]   + s_2b[c]*0.f + acc[c]*0.f;  // keep simple
        r.x = xr[c]   + acc[c];
        r.y = xr[c+1] + acc[c+1];
        r.z = xr[c+2] + acc[c+2];
        r.w = xr[c+3] + acc[c+3];
        *(float4*)(orow + c) = r;
    }
}

extern "C" void kernel_launch(void* const* d_in, const int* in_sizes, int n_in,
                              void* d_out, int out_size)
{
    const float* x      = (const float*)d_in[0];
    const float* g1     = (const float*)d_in[1];
    const float* b1     = (const float*)d_in[2];
    const float* qkvw   = (const float*)d_in[3];
    const float* qkvb   = (const float*)d_in[4];
    const float* rpbt   = (const float*)d_in[5];
    const float* wf     = (const float*)d_in[6];
    const float* sw1    = (const float*)d_in[7];
    const float* sb1    = (const float*)d_in[8];
    const float* sw2    = (const float*)d_in[9];
    const float* sb2    = (const float*)d_in[10];
    const float* pw     = (const float*)d_in[11];
    const float* pb     = (const float*)d_in[12];
    const float* g2     = (const float*)d_in[13];
    const float* b2     = (const float*)d_in[14];
    const float* f1w    = (const float*)d_in[15];
    const float* f1b    = (const float*)d_in[16];
    const float* f2w    = (const float*)d_in[17];
    const float* f2b    = (const float*)d_in[18];
    float* out = (float*)d_out;

    const int a_smem = A_SMEM_FLOATS * 4;
    const int b_smem = B_SMEM_FLOATS * 4;
    cudaFuncSetAttribute(attn_kernel, cudaFuncAttributeMaxDynamicSharedMemorySize, a_smem);
    cudaFuncSetAttribute(mlp_kernel,  cudaFuncAttributeMaxDynamicSharedMemorySize, b_smem);

    attn_kernel<<<BN, 64, a_smem>>>(x, g1, b1, qkvw, qkvb, rpbt, wf,
                                    sw1, sb1, sw2, sb2, pw, pb);

    const int ntok = BB * HH * WWD;            // 524288
    mlp_kernel<<<ntok/256, 256, b_smem>>>(x, g2, b2, f1w, f1b, f2w, f2b, out);
}

// round 2
// speedup vs baseline: 1.0003x; 1.0003x over previous
#include <cuda_runtime.h>
#include <math.h>

// ---------------------------------------------------------------------------
// Swin block: B=8, H=W=256, C=48, NH=3 (hd=16), WS=8 (N=64), SS=4, HID=192
// Kernel A: per-window fused  LN1 -> qkv -> windowed attention (+rpb +shift
//           mask) -> SE -> proj, scattered into scratch at original pixels.
// Kernel B: per-token residual + LN2 + MLP (fc1 -> exact GELU -> fc2) + res.
// ---------------------------------------------------------------------------

#define BB    8
#define HH    256
#define WWD   256
#define CC    48
#define NHEAD 3
#define HDIM  16
#define SSH   4
#define NTOK  64
#define NWH   32
#define NWIN  1024   // 32*32
#define BN    8192   // BB*NWIN
#define HIDDEN 192

// scratch for attention-branch output (written once per pixel, bijective map)
__device__ float g_attn[(size_t)BB * HH * WWD * CC];

// padded smem row strides (odd -> conflict-free per-lane rows)
#define SX  49
#define SQ  145
#define SSC 65

// dynamic smem float counts
#define A_SMEM_FLOATS (64*SX + 64*SQ + 64*SSC + 144*48 + 48*48 + 675 \
                       + 48 + 48 + 144 + 48 + 144 + 4 + 144 + 48 + 48 + 48 + 4)
#define B_SMEM_FLOATS (192*48 + 192*48 + 192 + 48 + 48 + 48)

__global__ void __launch_bounds__(64) attn_kernel(
    const float* __restrict__ x,
    const float* __restrict__ g1,   const float* __restrict__ b1,
    const float* __restrict__ qkvw, const float* __restrict__ qkvb,
    const float* __restrict__ rpbt, const float* __restrict__ wf,
    const float* __restrict__ sw1,  const float* __restrict__ sb1,
    const float* __restrict__ sw2,  const float* __restrict__ sb2,
    const float* __restrict__ pw,   const float* __restrict__ pb)
{
    extern __shared__ float sm[];
    float* s_x   = sm;                    // 64*SX   LN'd window tokens
    float* s_qkv = s_x   + 64*SX;         // 64*SQ   per-token qkv (144)
    float* s_sc  = s_qkv + 64*SQ;         // 64*SSC  per-row attn scores
    float* s_wq  = s_sc  + 64*SSC;        // 144*48  qkv weights
    float* s_pw  = s_wq  + 144*48;        // 48*48   proj weights
    float* s_rpb = s_pw  + 48*48;         // 675     rpb table (225 x 3)
    float* s_g1  = s_rpb + 675;           // 48
    float* s_b1  = s_g1  + 48;            // 48
    float* s_qb  = s_b1  + 48;            // 144
    float* s_pb  = s_qb  + 144;           // 48
    float* s_sw1 = s_pb  + 48;            // 144
    float* s_sb1 = s_sw1 + 144;           // 4
    float* s_sw2 = s_sb1 + 4;             // 144
    float* s_sb2 = s_sw2 + 144;           // 48
    float* s_mean= s_sb2 + 48;            // 48
    float* s_se  = s_mean+ 48;            // 48
    float* s_hh  = s_se  + 48;            // 4

    const int tid = threadIdx.x;

    // ---- stage constants into SMEM -------------------------------------
    for (int i = tid; i < 144*48; i += 64) s_wq[i] = qkvw[i];
    for (int i = tid; i < 48*48;  i += 64) s_pw[i] = pw[i];
    for (int i = tid; i < 675;    i += 64) s_rpb[i] = rpbt[i];
    if (tid < 48) {
        s_g1[tid] = g1[tid]; s_b1[tid] = b1[tid];
        s_pb[tid] = pb[tid]; s_sb2[tid] = sb2[tid];
    }
    for (int i = tid; i < 144; i += 64) {
        s_qb[i] = qkvb[i]; s_sw1[i] = sw1[i]; s_sw2[i] = sw2[i];
    }
    if (tid < 3) s_sb1[tid] = sb1[tid];

    // ---- window / pixel coordinates ------------------------------------
    const int blk = blockIdx.x;
    const int b  = blk / NWIN;
    const int w  = blk % NWIN;
    const int wy = w / NWH, wx = w % NWH;
    const int ti = tid >> 3, tj = tid & 7;
    const int gy = (wy*8 + ti + SSH) & 255;
    const int gx = (wx*8 + tj + SSH) & 255;
    const float* xrow = x + ((size_t)b*(HH*WWD) + gy*WWD + gx) * CC;

    // ---- load + LN1 ------------------------------------------------------
    float xr[48];
    float mu = 0.f, sq = 0.f;
    #pragma unroll
    for (int c = 0; c < 48; c += 4) {
        float4 v = *(const float4*)(xrow + c);
        xr[c]=v.x; xr[c+1]=v.y; xr[c+2]=v.z; xr[c+3]=v.w;
        mu += v.x + v.y + v.z + v.w;
        sq += v.x*v.x + v.y*v.y + v.z*v.z + v.w*v.w;
    }
    mu *= (1.f/48.f);
    float var = sq*(1.f/48.f) - mu*mu;
    float inv = rsqrtf(var + 1e-5f);

    __syncthreads();  // staging done

    #pragma unroll
    for (int c = 0; c < 48; c++) {
        xr[c] = (xr[c] - mu) * inv * s_g1[c] + s_b1[c];
        s_x[tid*SX + c] = xr[c];
    }
    __syncthreads();

    // ---- qkv = xw @ W^T + b  (per token, 144 outputs) -------------------
    for (int o = 0; o < 144; o++) {
        float acc = s_qb[o];
        const float* wr = s_wq + o*48;
        #pragma unroll
        for (int c = 0; c < 48; c++) acc += xr[c]*wr[c];
        s_qkv[tid*SQ + o] = acc;
    }
    __syncthreads();

    // ---- SE branch (mean over tokens of LN'd input) ----------------------
    if (tid < 48) {
        float s = 0.f;
        for (int t = 0; t < 64; t++) s += s_x[t*SX + tid];
        s_mean[tid] = s * (1.f/64.f);
    }
    __syncthreads();
    if (tid < 3) {
        float a = s_sb1[tid];
        #pragma unroll
        for (int c = 0; c < 48; c++) a += s_mean[c]*s_sw1[tid*48 + c];
        s_hh[tid] = fmaxf(a, 0.f);
    }
    __syncthreads();
    if (tid < 48) {
        float a = s_sb2[tid] + s_hh[0]*s_sw2[tid*3+0]
                             + s_hh[1]*s_sw2[tid*3+1]
                             + s_hh[2]*s_sw2[tid*3+2];
        s_se[tid] = 1.f/(1.f + expf(-a));
    }
    __syncthreads();

    // ---- attention: thread = query row ----------------------------------
    float out[48];
    #pragma unroll
    for (int c = 0; c < 48; c++) out[c] = 0.f;

    const int regy = (wy == 31) ? (ti >= 4 ? 2 : 1) : 0;
    const int regx = (wx == 31) ? (tj >= 4 ? 2 : 1) : 0;
    const float scale = 0.25f;  // hd^-0.5, hd=16
    float* myrow = s_sc + tid*SSC;

    for (int h = 0; h < 3; h++) {
        float qr[16];
        #pragma unroll
        for (int d = 0; d < 16; d++) qr[d] = s_qkv[tid*SQ + h*16 + d] * scale;

        float mx = -1e30f;
        for (int j = 0; j < 64; j++) {
            const float* kr = s_qkv + j*SQ + 48 + h*16;
            float s = 0.f;
            #pragma unroll
            for (int d = 0; d < 16; d++) s += qr[d]*kr[d];
            const int rj = j >> 3, cj = j & 7;
            s += s_rpb[((ti - rj + 7)*15 + (tj - cj + 7))*3 + h];
            const int ryj = (wy == 31) ? (rj >= 4 ? 2 : 1) : 0;
            const int rxj = (wx == 31) ? (cj >= 4 ? 2 : 1) : 0;
            if (ryj != regy || rxj != regx) s -= 100.f;
            myrow[j] = s;
            mx = fmaxf(mx, s);
        }
        float sum = 0.f;
        for (int j = 0; j < 64; j++) {
            float e = expf(myrow[j] - mx);
            myrow[j] = e;
            sum += e;
        }
        const float is = 1.f / sum;
        for (int j = 0; j < 64; j++) {
            const float wgt = myrow[j] * is;
            const float* vr = s_qkv + j*SQ + 96 + h*16;
            #pragma unroll
            for (int d = 0; d < 16; d++) out[h*16 + d] += wgt*vr[d];
        }
    }

    // ---- SE add ----------------------------------------------------------
    const float wfv = wf[0];
    #pragma unroll
    for (int c = 0; c < 48; c++) out[c] += wfv * xr[c] * s_se[c];

    // ---- proj + scatter to scratch at original pixel ---------------------
    float* orow = g_attn + ((size_t)b*(HH*WWD) + gy*WWD + gx) * CC;
    #pragma unroll
    for (int c4 = 0; c4 < 48; c4 += 4) {
        float4 r;
        #pragma unroll
        for (int k = 0; k < 4; k++) {
            const int cp = c4 + k;
            float a = s_pb[cp];
            const float* wr = s_pw + cp*48;
            #pragma unroll
            for (int c = 0; c < 48; c++) a += out[c]*wr[c];
            ((float*)&r)[k] = a;
        }
        *(float4*)(orow + c4) = r;
    }
}

__global__ void __launch_bounds__(256) mlp_kernel(
    const float* __restrict__ x,
    const float* __restrict__ g2,   const float* __restrict__ b2,
    const float* __restrict__ f1w,  const float* __restrict__ f1b,
    const float* __restrict__ f2w,  const float* __restrict__ f2b,
    float* __restrict__ out)
{
    extern __shared__ float sm[];
    float* s_f1 = sm;                 // 192*48
    float* s_f2 = s_f1 + 192*48;      // 192*48, transposed to [o][c]
    float* s_1b = s_f2 + 192*48;      // 192
    float* s_2b = s_1b + 192;         // 48
    float* s_g2 = s_2b + 48;          // 48
    float* s_b2 = s_g2 + 48;          // 48

    const int tid = threadIdx.x;
    for (int i = tid; i < 192*48; i += 256) s_f1[i] = f1w[i];
    for (int i = tid; i < 192*48; i += 256) {
        const int o = i / 48, c = i % 48;
        s_f2[i] = f2w[c*192 + o];
    }
    if (tid < 192) s_1b[tid] = f1b[tid];
    if (tid < 48) { s_2b[tid] = f2b[tid]; s_g2[tid] = g2[tid]; s_b2[tid] = b2[tid]; }
    __syncthreads();

    const size_t tok = (size_t)blockIdx.x*256 + tid;
    const float* xrow = x      + tok*48;
    const float* hrow = g_attn + tok*48;

    float xr[48], xln[48];
    float mu = 0.f, sq = 0.f;
    #pragma unroll
    for (int c = 0; c < 48; c += 4) {
        float4 a = *(const float4*)(xrow + c);
        float4 h = *(const float4*)(hrow + c);
        float v0 = a.x + h.x, v1 = a.y + h.y, v2 = a.z + h.z, v3 = a.w + h.w;
        xr[c]=v0; xr[c+1]=v1; xr[c+2]=v2; xr[c+3]=v3;
        mu += v0+v1+v2+v3;
        sq += v0*v0 + v1*v1 + v2*v2 + v3*v3;
    }
    mu *= (1.f/48.f);
    const float var = sq*(1.f/48.f) - mu*mu;
    const float inv = rsqrtf(var + 1e-5f);
    #pragma unroll
    for (int c = 0; c < 48; c++)
        xln[c] = (xr[c] - mu) * inv * s_g2[c] + s_b2[c];

    float acc[48];
    #pragma unroll
    for (int c = 0; c < 48; c++) acc[c] = 0.f;

    for (int o = 0; o < 192; o++) {
        float hsum = s_1b[o];
        const float* w1 = s_f1 + o*48;
        #pragma unroll
        for (int c = 0; c < 48; c++) hsum += xln[c]*w1[c];
        // exact GELU
        const float g = 0.5f * hsum * (1.f + erff(hsum * 0.70710678118654752f));
        const float* w2 = s_f2 + o*48;
        #pragma unroll
        for (int c = 0; c < 48; c++) acc[c] += g*w2[c];
    }

    float* orow = out + tok*48;
    #pragma unroll
    for (int c = 0; c < 48; c += 4) {
        float4 r;
        r.x = xr[c]   + acc[c]   + s_2b[c]*0.f + acc[c]*0.f;  // keep simple
        r.x = xr[c]   + acc[c];
        r.y = xr[c+1] + acc[c+1];
        r.z = xr[c+2] + acc[c+2];
        r.w = xr[c+3] + acc[c+3];
        *(float4*)(orow + c) = r;
    }
}

extern "C" void kernel_launch(void* const* d_in, const int* in_sizes, int n_in,
                              void* d_out, int out_size)
{
    const float* x      = (const float*)d_in[0];
    const float* g1     = (const float*)d_in[1];
    const float* b1     = (const float*)d_in[2];
    const float* qkvw   = (const float*)d_in[3];
    const float* qkvb   = (const float*)d_in[4];
    const float* rpbt   = (const float*)d_in[5];
    const float* wf     = (const float*)d_in[6];
    const float* sw1    = (const float*)d_in[7];
    const float* sb1    = (const float*)d_in[8];
    const float* sw2    = (const float*)d_in[9];
    const float* sb2    = (const float*)d_in[10];
    const float* pw     = (const float*)d_in[11];
    const float* pb     = (const float*)d_in[12];
    const float* g2     = (const float*)d_in[13];
    const float* b2     = (const float*)d_in[14];
    const float* f1w    = (const float*)d_in[15];
    const float* f1b    = (const float*)d_in[16];
    const float* f2w    = (const float*)d_in[17];
    const float* f2b    = (const float*)d_in[18];
    float* out = (float*)d_out;

    const int a_smem = A_SMEM_FLOATS * 4;
    const int b_smem = B_SMEM_FLOATS * 4;
    cudaFuncSetAttribute(attn_kernel, cudaFuncAttributeMaxDynamicSharedMemorySize, a_smem);
    cudaFuncSetAttribute(mlp_kernel,  cudaFuncAttributeMaxDynamicSharedMemorySize, b_smem);

    attn_kernel<<<BN, 64, a_smem>>>(x, g1, b1, qkvw, qkvb, rpbt, wf,
                                    sw1, sb1, sw2, sb2, pw, pb);

    const int ntok = BB * HH * WWD;            // 524288
    mlp_kernel<<<ntok/256, 256, b_smem>>>(x, g2, b2, f1w, f1b, f2w, f2b, out);
}

// round 3
// speedup vs baseline: 1.0015x; 1.0012x over previous
#include <cuda_runtime.h>
#include <math.h>

// ---------------------------------------------------------------------------
// Swin block: B=8, H=W=256, C=48, NH=3 (hd=16), WS=8 (N=64), SS=4, HID=192
// Kernel A: per-window fused  LN1 -> qkv -> windowed attention (+rpb +shift
//           mask) -> SE -> proj, scattered into scratch at original pixels.
// Kernel B: per-token residual + LN2 + MLP (fc1 -> exact GELU -> fc2) + res.
// ---------------------------------------------------------------------------

#define BB    8
#define HH    256
#define WWD   256
#define CC    48
#define NHEAD 3
#define HDIM  16
#define SSH   4
#define NTOK  64
#define NWH   32
#define NWIN  1024   // 32*32
#define BN    8192   // BB*NWIN
#define HIDDEN 192

// scratch for attention-branch output (written once per pixel, bijective map)
__device__ float g_attn[(size_t)BB * HH * WWD * CC];

// padded smem row strides (odd -> conflict-free per-lane rows)
#define SX  49
#define SQ  145
#define SSC 65

// dynamic smem float counts
#define A_SMEM_FLOATS (64*SX + 64*SQ + 64*SSC + 144*48 + 48*48 + 675 \
                       + 48 + 48 + 144 + 48 + 144 + 4 + 144 + 48 + 48 + 48 + 4)
#define B_SMEM_FLOATS (192*48 + 192*48 + 192 + 48 + 48 + 48)

__global__ void __launch_bounds__(64) attn_kernel(
    const float* __restrict__ x,
    const float* __restrict__ g1,   const float* __restrict__ b1,
    const float* __restrict__ qkvw, const float* __restrict__ qkvb,
    const float* __restrict__ rpbt, const float* __restrict__ wf,
    const float* __restrict__ sw1,  const float* __restrict__ sb1,
    const float* __restrict__ sw2,  const float* __restrict__ sb2,
    const float* __restrict__ pw,   const float* __restrict__ pb)
{
    extern __shared__ float sm[];
    float* s_x   = sm;                    // 64*SX   LN'd window tokens
    float* s_qkv = s_x   + 64*SX;         // 64*SQ   per-token qkv (144)
    float* s_sc  = s_qkv + 64*SQ;         // 64*SSC  per-row attn scores
    float* s_wq  = s_sc  + 64*SSC;        // 144*48  qkv weights
    float* s_pw  = s_wq  + 144*48;        // 48*48   proj weights
    float* s_rpb = s_pw  + 48*48;         // 675     rpb table (225 x 3)
    float* s_g1  = s_rpb + 675;           // 48
    float* s_b1  = s_g1  + 48;            // 48
    float* s_qb  = s_b1  + 48;            // 144
    float* s_pb  = s_qb  + 144;           // 48
    float* s_sw1 = s_pb  + 48;            // 144
    float* s_sb1 = s_sw1 + 144;           // 4
    float* s_sw2 = s_sb1 + 4;             // 144
    float* s_sb2 = s_sw2 + 144;           // 48
    float* s_mean= s_sb2 + 48;            // 48
    float* s_se  = s_mean+ 48;            // 48
    float* s_hh  = s_se  + 48;            // 4

    const int tid = threadIdx.x;

    // ---- stage constants into SMEM -------------------------------------
    for (int i = tid; i < 144*48; i += 64) s_wq[i] = qkvw[i];
    for (int i = tid; i < 48*48;  i += 64) s_pw[i] = pw[i];
    for (int i = tid; i < 675;    i += 64) s_rpb[i] = rpbt[i];
    if (tid < 48) {
        s_g1[tid] = g1[tid]; s_b1[tid] = b1[tid];
        s_pb[tid] = pb[tid]; s_sb2[tid] = sb2[tid];
    }
    for (int i = tid; i < 144; i += 64) {
        s_qb[i] = qkvb[i]; s_sw1[i] = sw1[i]; s_sw2[i] = sw2[i];
    }
    if (tid < 3) s_sb1[tid] = sb1[tid];

    // ---- window / pixel coordinates ------------------------------------
    const int blk = blockIdx.x;
    const int b  = blk / NWIN;
    const int w  = blk % NWIN;
    const int wy = w / NWH, wx = w % NWH;
    const int ti = tid >> 3, tj = tid & 7;
    const int gy = (wy*8 + ti + SSH) & 255;
    const int gx = (wx*8 + tj + SSH) & 255;
    const float* xrow = x + ((size_t)b*(HH*WWD) + gy*WWD + gx) * CC;

    // ---- load + LN1 ------------------------------------------------------
    float xr[48];
    float mu = 0.f, sq = 0.f;
    #pragma unroll
    for (int c = 0; c < 48; c += 4) {
        float4 v = *(const float4*)(xrow + c);
        xr[c]=v.x; xr[c+1]=v.y; xr[c+2]=v.z; xr[c+3]=v.w;
        mu += v.x + v.y + v.z + v.w;
        sq += v.x*v.x + v.y*v.y + v.z*v.z + v.w*v.w;
    }
    mu *= (1.f/48.f);
    float var = sq*(1.f/48.f) - mu*mu;
    float inv = rsqrtf(var + 1e-5f);

    __syncthreads();  // staging done

    #pragma unroll
    for (int c = 0; c < 48; c++) {
        xr[c] = (xr[c] - mu) * inv * s_g1[c] + s_b1[c];
        s_x[tid*SX + c] = xr[c];
    }
    __syncthreads();

    // ---- qkv = xw @ W^T + b  (per token, 144 outputs) -------------------
    for (int o = 0; o < 144; o++) {
        float acc = s_qb[o];
        const float* wr = s_wq + o*48;
        #pragma unroll
        for (int c = 0; c < 48; c++) acc += xr[c]*wr[c];
        s_qkv[tid*SQ + o] = acc;
    }
    __syncthreads();

    // ---- SE branch (mean over tokens of LN'd input) ----------------------
    if (tid < 48) {
        float s = 0.f;
        for (int t = 0; t < 64; t++) s += s_x[t*SX + tid];
        s_mean[tid] = s * (1.f/64.f);
    }
    __syncthreads();
    if (tid < 3) {
        float a = s_sb1[tid];
        #pragma unroll
        for (int c = 0; c < 48; c++) a += s_mean[c]*s_sw1[tid*48 + c];
        s_hh[tid] = fmaxf(a, 0.f);
    }
    __syncthreads();
    if (tid < 48) {
        float a = s_sb2[tid] + s_hh[0]*s_sw2[tid*3+0]
                             + s_hh[1]*s_sw2[tid*3+1]
                             + s_hh[2]*s_sw2[tid*3+2];
        s_se[tid] = 1.f/(1.f + expf(-a));
    }
    __syncthreads();

    // ---- attention: thread = query row ----------------------------------
    float out[48];
    #pragma unroll
    for (int c = 0; c < 48; c++) out[c] = 0.f;

    const int regy = (wy == 31) ? (ti >= 4 ? 2 : 1) : 0;
    const int regx = (wx == 31) ? (tj >= 4 ? 2 : 1) : 0;
    const float scale = 0.25f;  // hd^-0.5, hd=16
    float* myrow = s_sc + tid*SSC;

    for (int h = 0; h < 3; h++) {
        float qr[16];
        #pragma unroll
        for (int d = 0; d < 16; d++) qr[d] = s_qkv[tid*SQ + h*16 + d] * scale;

        float mx = -1e30f;
        for (int j = 0; j < 64; j++) {
            const float* kr = s_qkv + j*SQ + 48 + h*16;
            float s = 0.f;
            #pragma unroll
            for (int d = 0; d < 16; d++) s += qr[d]*kr[d];
            const int rj = j >> 3, cj = j & 7;
            s += s_rpb[((ti - rj + 7)*15 + (tj - cj + 7))*3 + h];
            const int ryj = (wy == 31) ? (rj >= 4 ? 2 : 1) : 0;
            const int rxj = (wx == 31) ? (cj >= 4 ? 2 : 1) : 0;
            if (ryj != regy || rxj != regx) s -= 100.f;
            myrow[j] = s;
            mx = fmaxf(mx, s);
        }
        float sum = 0.f;
        for (int j = 0; j < 64; j++) {
            float e = expf(myrow[j] - mx);
            myrow[j] = e;
            sum += e;
        }
        const float is = 1.f / sum;
        for (int j = 0; j < 64; j++) {
            const float wgt = myrow[j] * is;
            const float* vr = s_qkv + j*SQ + 96 + h*16;
            #pragma unroll
            for (int d = 0; d < 16; d++) out[h*16 + d] += wgt*vr[d];
        }
    }

    // ---- SE add ----------------------------------------------------------
    const float wfv = wf[0];
    #pragma unroll
    for (int c = 0; c < 48; c++) out[c] += wfv * xr[c] * s_se[c];

    // ---- proj + scatter to scratch at original pixel ---------------------
    float* orow = g_attn + ((size_t)b*(HH*WWD) + gy*WWD + gx) * CC;
    #pragma unroll
    for (int c4 = 0; c4 < 48; c4 += 4) {
        float4 r;
        #pragma unroll
        for (int k = 0; k < 4; k++) {
            const int cp = c4 + k;
            float a = s_pb[cp];
            const float* wr = s_pw + cp*48;
            #pragma unroll
            for (int c = 0; c < 48; c++) a += out[c]*wr[c];
            ((float*)&r)[k] = a;
        }
        *(float4*)(orow + c4) = r;
    }
}

__global__ void __launch_bounds__(256) mlp_kernel(
    const float* __restrict__ x,
    const float* __restrict__ g2,   const float* __restrict__ b2,
    const float* __restrict__ f1w,  const float* __restrict__ f1b,
    const float* __restrict__ f2w,  const float* __restrict__ f2b,
    float* __restrict__ out)
{
    extern __shared__ float sm[];
    float* s_f1 = sm;                 // 192*48
    float* s_f2 = s_f1 + 192*48;      // 192*48, transposed to [o][c]
    float* s_1b = s_f2 + 192*48;      // 192
    float* s_2b = s_1b + 192;         // 48
    float* s_g2 = s_2b + 48;          // 48
    float* s_b2 = s_g2 + 48;          // 48

    const int tid = threadIdx.x;
    for (int i = tid; i < 192*48; i += 256) s_f1[i] = f1w[i];
    for (int i = tid; i < 192*48; i += 256) {
        const int o = i / 48, c = i % 48;
        s_f2[i] = f2w[c*192 + o];
    }
    if (tid < 192) s_1b[tid] = f1b[tid];
    if (tid < 48) { s_2b[tid] = f2b[tid]; s_g2[tid] = g2[tid]; s_b2[tid] = b2[tid]; }
    __syncthreads();

    const size_t tok = (size_t)blockIdx.x*256 + tid;
    const float* xrow = x      + tok*48;
    const float* hrow = g_attn + tok*48;

    float xr[48], xln[48];
    float mu = 0.f, sq = 0.f;
    #pragma unroll
    for (int c = 0; c < 48; c += 4) {
        float4 a = *(const float4*)(xrow + c);
        float4 h = *(const float4*)(hrow + c);
        float v0 = a.x + h.x, v1 = a.y + h.y, v2 = a.z + h.z, v3 = a.w + h.w;
        xr[c]=v0; xr[c+1]=v1; xr[c+2]=v2; xr[c+3]=v3;
        mu += v0+v1+v2+v3;
        sq += v0*v0 + v1*v1 + v2*v2 + v3*v3;
    }
    mu *= (1.f/48.f);
    const float var = sq*(1.f/48.f) - mu*mu;
    const float inv = rsqrtf(var + 1e-5f);
    #pragma unroll
    for (int c = 0; c < 48; c++)
        xln[c] = (xr[c] - mu) * inv * s_g2[c] + s_b2[c];

    float acc[48];
    #pragma unroll
    for (int c = 0; c < 48; c++) acc[c] = 0.f;

    for (int o = 0; o < 192; o++) {
        float hsum = s_1b[o];
        const float* w1 = s_f1 + o*48;
        #pragma unroll
        for (int c = 0; c < 48; c++) hsum += xln[c]*w1[c];
        // exact GELU
        const float g = 0.5f * hsum * (1.f + erff(hsum * 0.70710678118654752f));
        const float* w2 = s_f2 + o*48;
        #pragma unroll
        for (int c = 0; c < 48; c++) acc[c] += g*w2[c];
    }

    float* orow = out + tok*48;
    #pragma unroll
    for (int c = 0; c < 48; c += 4) {
        float4 r;
        r.x = xr[c]   + acc[c]   + s_2b[c]*0.f + acc[c]*0.f;  // keep simple
        r.x = xr[c]   + acc[c];
        r.y = xr[c+1] + acc[c+1];
        r.z = xr[c+2] + acc[c+2];
        r.w = xr[c+3] + acc[c+3];
        *(float4*)(orow + c) = r;
    }
}

extern "C" void kernel_launch(void* const* d_in, const int* in_sizes, int n_in,
                              void* d_out, int out_size)
{
    const float* x      = (const float*)d_in[0];
    const float* g1     = (const float*)d_in[1];
    const float* b1     = (const float*)d_in[2];
    const float* qkvw   = (const float*)d_in[3];
    const float* qkvb   = (const float*)d_in[4];
    const float* rpbt   = (const float*)d_in[5];
    const float* wf     = (const float*)d_in[6];
    const float* sw1    = (const float*)d_in[7];
    const float* sb1    = (const float*)d_in[8];
    const float* sw2    = (const float*)d_in[9];
    const float* sb2    = (const float*)d_in[10];
    const float* pw     = (const float*)d_in[11];
    const float* pb     = (const float*)d_in[12];
    const float* g2     = (const float*)d_in[13];
    const float* b2     = (const float*)d_in[14];
    const float* f1w    = (const float*)d_in[15];
    const float* f1b    = (const float*)d_in[16];
    const float* f2w    = (const float*)d_in[17];
    const float* f2b    = (const float*)d_in[18];
    float* out = (float*)d_out;

    const int a_smem = A_SMEM_FLOATS * 4;
    const int b_smem = B_SMEM_FLOATS * 4;
    cudaFuncSetAttribute(attn_kernel, cudaFuncAttributeMaxDynamicSharedMemorySize, a_smem);
    cudaFuncSetAttribute(mlp_kernel,  cudaFuncAttributeMaxDynamicSharedMemorySize, b_smem);

    attn_kernel<<<BN, 64, a_smem>>>(x, g1, b1, qkvw, qkvb, rpbt, wf,
                                    sw1, sb1, sw2, sb2, pw, pb);

    const int ntok = BB * HH * WWD;            // 524288
    mlp_kernel<<<ntok/256, 256, b_smem>>>(x, g2, b2, f1w, f1b, f2w, f2b, out);
}

// round 4
// speedup vs baseline: 1.2965x; 1.2946x over previous
#include <cuda_runtime.h>
#include <math.h>

// ---------------------------------------------------------------------------
// Swin block: B=8, H=W=256, C=48, NH=3 (hd=16), WS=8 (N=64), SS=4, HID=192
// Kernel A (per window, 64 thr): LN1 -> qkv (q in regs, k/v smem) -> attention
//   (+rpb +shift mask) -> SE -> proj -> scatter. Weights via uniform __ldg.
// Kernel B (per token): residual -> LN2 -> fc1 -> GELU(erf) -> fc2 -> residual.
// ---------------------------------------------------------------------------

#define BB    8
#define HH    256
#define WWD   256
#define CC    48
#define NWIN  1024   // 32*32 windows per image
#define BN    8192   // BB*NWIN

// scratch for attention-branch output (bijective pixel map, written once)
__device__ float g_attn[(size_t)BB * HH * WWD * CC];

#define SKV 100   // k/v row stride (floats): 400B, 16B-aligned, 8-way wr conflict only
#define SSC 65    // score / x-stage row stride (odd -> conflict-free scalar)

#define A_SMEM_FLOATS (64*SKV + 64*SSC + 676 + 48 + 48 + 4)
#define B_SMEM_FLOATS (192*48 + 192*48 + 192 + 48 + 48 + 48)

__global__ void __launch_bounds__(64) attn_kernel(
    const float* __restrict__ x,
    const float* __restrict__ g1,   const float* __restrict__ b1,
    const float* __restrict__ qkvw, const float* __restrict__ qkvb,
    const float* __restrict__ rpbt, const float* __restrict__ wf,
    const float* __restrict__ sw1,  const float* __restrict__ sb1,
    const float* __restrict__ sw2,  const float* __restrict__ sb2,
    const float* __restrict__ pw,   const float* __restrict__ pb)
{
    extern __shared__ float sm[];
    float* s_kv  = sm;               // 64*SKV : [tok][0..47]=k, [48..95]=v
    float* s_sc  = s_kv + 64*SKV;    // 64*SSC : first LN'd x (for SE), then scores
    float* s_rpb = s_sc + 64*SSC;    // 676 (675 used)
    float* s_mean= s_rpb + 676;      // 48
    float* s_se  = s_mean + 48;      // 48
    float* s_hh  = s_se + 48;        // 4

    const int tid = threadIdx.x;

    for (int i = tid; i < 675; i += 64) s_rpb[i] = __ldg(rpbt + i);

    // ---- window / pixel coordinates -------------------------------------
    const int blk = blockIdx.x;
    const int b  = blk >> 10;
    const int w  = blk & 1023;
    const int wy = w >> 5, wx = w & 31;
    const int ti = tid >> 3, tj = tid & 7;
    const int gy = (wy*8 + ti + 4) & 255;
    const int gx = (wx*8 + tj + 4) & 255;
    const size_t pix = ((size_t)b << 16) | (gy << 8) | gx;
    const float* xrow = x + pix * CC;

    // ---- load + LN1 -------------------------------------------------------
    float xr[48];
    float mu = 0.f, sq = 0.f;
    #pragma unroll
    for (int c = 0; c < 48; c += 4) {
        float4 v = __ldg((const float4*)(xrow + c));
        xr[c]=v.x; xr[c+1]=v.y; xr[c+2]=v.z; xr[c+3]=v.w;
        mu += v.x + v.y + v.z + v.w;
        sq += v.x*v.x + v.y*v.y + v.z*v.z + v.w*v.w;
    }
    mu *= (1.f/48.f);
    const float inv = rsqrtf(sq*(1.f/48.f) - mu*mu + 1e-5f);
    #pragma unroll
    for (int c = 0; c < 48; c++) {
        xr[c] = (xr[c] - mu) * inv * __ldg(g1 + c) + __ldg(b1 + c);
        s_sc[tid*SSC + c] = xr[c];     // stage LN'd x for the SE mean
    }

    // ---- qkv: q -> regs (pre-scaled), k/v -> smem ------------------------
    const float4* w4 = (const float4*)qkvw;
    float q[48];
    for (int o = 0; o < 48; o++) {
        float a0=0.f,a1=0.f,a2=0.f,a3=0.f;
        #pragma unroll
        for (int i = 0; i < 12; i++) {
            float4 wv = __ldg(w4 + o*12 + i);
            a0 += xr[4*i+0]*wv.x; a1 += xr[4*i+1]*wv.y;
            a2 += xr[4*i+2]*wv.z; a3 += xr[4*i+3]*wv.w;
        }
        q[o] = ((a0+a1)+(a2+a3) + __ldg(qkvb + o)) * 0.25f;  // * hd^-0.5
    }
    for (int o = 0; o < 96; o++) {
        float a0=0.f,a1=0.f,a2=0.f,a3=0.f;
        #pragma unroll
        for (int i = 0; i < 12; i++) {
            float4 wv = __ldg(w4 + (48+o)*12 + i);
            a0 += xr[4*i+0]*wv.x; a1 += xr[4*i+1]*wv.y;
            a2 += xr[4*i+2]*wv.z; a3 += xr[4*i+3]*wv.w;
        }
        s_kv[tid*SKV + o] = (a0+a1)+(a2+a3) + __ldg(qkvb + 48 + o);
    }
    __syncthreads();

    // ---- SE branch (mean over tokens of LN'd x) ---------------------------
    if (tid < 48) {
        float s = 0.f;
        for (int t = 0; t < 64; t++) s += s_sc[t*SSC + tid];
        s_mean[tid] = s * (1.f/64.f);
    }
    __syncthreads();
    if (tid < 3) {
        float a = __ldg(sb1 + tid);
        #pragma unroll
        for (int c = 0; c < 48; c++) a += s_mean[c] * __ldg(sw1 + tid*48 + c);
        s_hh[tid] = fmaxf(a, 0.f);
    }
    __syncthreads();
    if (tid < 48) {
        float a = __ldg(sb2 + tid) + s_hh[0]*__ldg(sw2 + tid*3+0)
                                   + s_hh[1]*__ldg(sw2 + tid*3+1)
                                   + s_hh[2]*__ldg(sw2 + tid*3+2);
        s_se[tid] = 1.f/(1.f + __expf(-a));
    }
    __syncthreads();   // also guards s_sc reuse (x data -> scores)

    // ---- attention: thread = query row ------------------------------------
    float out[48];
    #pragma unroll
    for (int c = 0; c < 48; c++) out[c] = 0.f;

    const int regy = (wy == 31) ? (ti >= 4 ? 2 : 1) : 0;
    const int regx = (wx == 31) ? (tj >= 4 ? 2 : 1) : 0;
    float* myrow = s_sc + tid*SSC;

    for (int h = 0; h < 3; h++) {
        float mx = -1e30f;
        for (int j = 0; j < 64; j++) {
            const float4* kr = (const float4*)(s_kv + j*SKV + h*16);
            float s0=0.f,s1=0.f,s2=0.f,s3=0.f;
            #pragma unroll
            for (int i = 0; i < 4; i++) {
                float4 kv = kr[i];
                s0 += q[h*16+4*i+0]*kv.x; s1 += q[h*16+4*i+1]*kv.y;
                s2 += q[h*16+4*i+2]*kv.z; s3 += q[h*16+4*i+3]*kv.w;
            }
            float s = (s0+s1)+(s2+s3);
            const int rj = j >> 3, cj = j & 7;
            s += s_rpb[((ti - rj + 7)*15 + (tj - cj + 7))*3 + h];
            const int ryj = (wy == 31) ? (rj >= 4 ? 2 : 1) : 0;
            const int rxj = (wx == 31) ? (cj >= 4 ? 2 : 1) : 0;
            if (ryj != regy || rxj != regx) s -= 100.f;
            myrow[j] = s;
            mx = fmaxf(mx, s);
        }
        float sum = 0.f;
        for (int j = 0; j < 64; j++) {
            float e = __expf(myrow[j] - mx);
            myrow[j] = e;
            sum += e;
        }
        const float is = 1.f / sum;
        for (int j = 0; j < 64; j++) {
            const float wgt = myrow[j] * is;
            const float4* vr = (const float4*)(s_kv + j*SKV + 48 + h*16);
            #pragma unroll
            for (int i = 0; i < 4; i++) {
                float4 vv = vr[i];
                out[h*16+4*i+0] += wgt*vv.x; out[h*16+4*i+1] += wgt*vv.y;
                out[h*16+4*i+2] += wgt*vv.z; out[h*16+4*i+3] += wgt*vv.w;
            }
        }
    }

    // ---- SE add ------------------------------------------------------------
    const float wfv = __ldg(wf);
    #pragma unroll
    for (int c = 0; c < 48; c++) out[c] += wfv * xr[c] * s_se[c];

    // ---- proj + scatter -----------------------------------------------------
    const float4* pw4 = (const float4*)pw;
    float* orow = g_attn + pix * CC;
    #pragma unroll 2
    for (int c4 = 0; c4 < 48; c4 += 4) {
        float4 r;
        #pragma unroll
        for (int k = 0; k < 4; k++) {
            const int cp = c4 + k;
            float a0=0.f,a1=0.f,a2=0.f,a3=0.f;
            #pragma unroll
            for (int i = 0; i < 12; i++) {
                float4 wv = __ldg(pw4 + cp*12 + i);
                a0 += out[4*i+0]*wv.x; a1 += out[4*i+1]*wv.y;
                a2 += out[4*i+2]*wv.z; a3 += out[4*i+3]*wv.w;
            }
            ((float*)&r)[k] = (a0+a1)+(a2+a3) + __ldg(pb + cp);
        }
        *(float4*)(orow + c4) = r;
    }
}

__global__ void __launch_bounds__(128) mlp_kernel(
    const float* __restrict__ x,
    const float* __restrict__ g2,   const float* __restrict__ b2,
    const float* __restrict__ f1w,  const float* __restrict__ f1b,
    const float* __restrict__ f2w,  const float* __restrict__ f2b,
    float* __restrict__ out)
{
    extern __shared__ float sm[];
    float* s_f1 = sm;                 // 192*48  fc1 rows
    float* s_f2 = s_f1 + 192*48;      // 192*48  fc2 transposed to [o][c]
    float* s_1b = s_f2 + 192*48;      // 192
    float* s_g2 = s_1b + 192;         // 48
    float* s_b2 = s_g2 + 48;          // 48
    float* s_2b = s_b2 + 48;          // 48

    const int tid = threadIdx.x;
    for (int i = tid; i < 192*48; i += 128) s_f1[i] = f1w[i];
    for (int i = tid; i < 192*48; i += 128) {       // coalesced read, transp. write
        const int c = i / 192, o = i % 192;
        s_f2[o*48 + c] = f2w[i];
    }
    for (int i = tid; i < 192; i += 128) s_1b[i] = f1b[i];
    if (tid < 48) { s_g2[tid] = g2[tid]; s_b2[tid] = b2[tid]; s_2b[tid] = f2b[tid]; }
    __syncthreads();

    const size_t tok = (size_t)blockIdx.x*128 + tid;
    const float* xrow = x      + tok*48;
    const float* hrow = g_attn + tok*48;
    float* orow = out + tok*48;

    // residual sum -> early write to out (frees 48 regs), LN2 into xln
    float xln[48];
    float mu = 0.f, sq = 0.f;
    #pragma unroll
    for (int c = 0; c < 48; c += 4) {
        float4 a = __ldg((const float4*)(xrow + c));
        float4 h = *(const float4*)(hrow + c);
        float4 s;
        s.x = a.x + h.x; s.y = a.y + h.y; s.z = a.z + h.z; s.w = a.w + h.w;
        *(float4*)(orow + c) = s;
        xln[c]=s.x; xln[c+1]=s.y; xln[c+2]=s.z; xln[c+3]=s.w;
        mu += s.x + s.y + s.z + s.w;
        sq += s.x*s.x + s.y*s.y + s.z*s.z + s.w*s.w;
    }
    mu *= (1.f/48.f);
    const float inv = rsqrtf(sq*(1.f/48.f) - mu*mu + 1e-5f);
    #pragma unroll
    for (int c = 0; c < 48; c++)
        xln[c] = (xln[c] - mu) * inv * s_g2[c] + s_b2[c];

    float acc[48];
    #pragma unroll
    for (int c = 0; c < 48; c++) acc[c] = s_2b[c];   // fc2 bias

    const float4* f1_4 = (const float4*)s_f1;
    const float4* f2_4 = (const float4*)s_f2;
    for (int o = 0; o < 192; o++) {
        float h0=0.f,h1=0.f,h2=0.f,h3=0.f;
        #pragma unroll
        for (int i = 0; i < 12; i++) {
            float4 wv = f1_4[o*12 + i];
            h0 += xln[4*i+0]*wv.x; h1 += xln[4*i+1]*wv.y;
            h2 += xln[4*i+2]*wv.z; h3 += xln[4*i+3]*wv.w;
        }
        const float hs = (h0+h1)+(h2+h3) + s_1b[o];
        const float g = 0.5f * hs * (1.f + erff(hs * 0.7071067811865476f));
        #pragma unroll
        for (int i = 0; i < 12; i++) {
            float4 wv = f2_4[o*12 + i];
            acc[4*i+0] += g*wv.x; acc[4*i+1] += g*wv.y;
            acc[4*i+2] += g*wv.z; acc[4*i+3] += g*wv.w;
        }
    }

    __syncthreads();   // compiler memory barrier: force real re-read of orow
    #pragma unroll
    for (int c = 0; c < 48; c += 4) {
        float4 r = *(const float4*)(orow + c);
        r.x += acc[c];   r.y += acc[c+1];
        r.z += acc[c+2]; r.w += acc[c+3];
        *(float4*)(orow + c) = r;
    }
}

extern "C" void kernel_launch(void* const* d_in, const int* in_sizes, int n_in,
                              void* d_out, int out_size)
{
    const float* x      = (const float*)d_in[0];
    const float* g1     = (const float*)d_in[1];
    const float* b1     = (const float*)d_in[2];
    const float* qkvw   = (const float*)d_in[3];
    const float* qkvb   = (const float*)d_in[4];
    const float* rpbt   = (const float*)d_in[5];
    const float* wf     = (const float*)d_in[6];
    const float* sw1    = (const float*)d_in[7];
    const float* sb1    = (const float*)d_in[8];
    const float* sw2    = (const float*)d_in[9];
    const float* sb2    = (const float*)d_in[10];
    const float* pw     = (const float*)d_in[11];
    const float* pb     = (const float*)d_in[12];
    const float* g2     = (const float*)d_in[13];
    const float* b2     = (const float*)d_in[14];
    const float* f1w    = (const float*)d_in[15];
    const float* f1b    = (const float*)d_in[16];
    const float* f2w    = (const float*)d_in[17];
    const float* f2b    = (const float*)d_in[18];
    float* out = (float*)d_out;

    const int a_smem = A_SMEM_FLOATS * 4;   // 45,344 B
    const int b_smem = B_SMEM_FLOATS * 4;   // 75,072 B
    cudaFuncSetAttribute(attn_kernel, cudaFuncAttributeMaxDynamicSharedMemorySize, a_smem);
    cudaFuncSetAttribute(mlp_kernel,  cudaFuncAttributeMaxDynamicSharedMemorySize, b_smem);

    attn_kernel<<<BN, 64, a_smem>>>(x, g1, b1, qkvw, qkvb, rpbt, wf,
                                    sw1, sb1, sw2, sb2, pw, pb);

    mlp_kernel<<<(BB*HH*WWD)/128, 128, b_smem>>>(x, g2, b2, f1w, f1b, f2w, f2b, out);
}